// round 10
// baseline (speedup 1.0000x reference)
#include <cuda_runtime.h>

// Problem constants
constexpr int Bn = 8;      // batch
constexpr int C  = 64;     // cin
constexpr int O  = 64;     // cout
constexpr int OL = 60;     // cout_lin
constexpr int H  = 256;
constexpr int W  = 256;
constexpr int R  = Bn * C * H;   // 131072 rows for forward dft-w
constexpr int NMODE = 32 * 16;   // 512 active modes (32 ky x 16 kx)

// Scratch (static device globals; allocation-free)
// g_X1 planar layout per row: [Re k=0..15 | Im k=0..15]
__device__ __align__(16) float  g_X1[R * 32];
__device__ __align__(16) float2 g_XF[Bn * C * 32 * 16];    // [b][c][j][kx]
__device__ __align__(16) float2 g_WT[NMODE * C * OL];      // [mode][i][o]
__device__ __align__(16) float2 g_OF[Bn * O * 32 * 16];    // [b][o][j][kx]
__device__ __align__(16) float  g_B1[128 * 32];            // fwd dft-w: [w][cos16|-sin16]
__device__ __align__(16) float  g_T5A[16 * 128];           // inv dft-w cos coeffs (incl 1/256)
__device__ __align__(16) float  g_T5B[16 * 128];           // inv dft-w sin coeffs (incl 1/256)

// Packed fp32x2 FMA (Blackwell): d = a*b + c elementwise on (x,y) lanes.
__device__ __forceinline__ float2 ffma2(float2 a, float2 b, float2 c) {
    float2 d;
    asm("{\n\t"
        ".reg .b64 ra, rb, rc;\n\t"
        "mov.b64 ra, {%2, %3};\n\t"
        "mov.b64 rb, {%4, %5};\n\t"
        "mov.b64 rc, {%6, %7};\n\t"
        "fma.rn.f32x2 rc, ra, rb, rc;\n\t"
        "mov.b64 {%0, %1}, rc;\n\t"
        "}"
        : "=f"(d.x), "=f"(d.y)
        : "f"(a.x), "f"(a.y), "f"(b.x), "f"(b.y), "f"(c.x), "f"(c.y));
    return d;
}

// ---------------------------------------------------------------------------
// K0a: twiddle tables
// ---------------------------------------------------------------------------
__global__ void k_tables() {
    int t = blockIdx.x * blockDim.x + threadIdx.x;
    if (t < 128 * 32) {
        int w = t >> 5, c = t & 31;
        float s, cc;
        if (c < 16) {
            sincospif((float)(c * w) / 128.0f, &s, &cc);
            g_B1[t] = cc;                     // cos part (w=0 -> 1)
        } else {
            sincospif((float)((c - 16) * w) / 128.0f, &s, &cc);
            g_B1[t] = -s;                     // -sin part (w=0 -> 0)
        }
    } else if (t < 128 * 32 + 16 * 128) {
        int u = t - 128 * 32;
        int k = u >> 7, w = u & 127;
        float s, c;
        sincospif((float)(k * w) / 128.0f, &s, &c);
        if (k == 0) { g_T5A[u] = 1.0f / 256.0f; g_T5B[u] = 0.0f; }
        else        { g_T5A[u] = 2.0f * c / 256.0f; g_T5B[u] = -2.0f * s / 256.0f; }
    }
}

// ---------------------------------------------------------------------------
// K0b: transpose weights into per-mode [i][o] complex layout (coalesced reads)
// ---------------------------------------------------------------------------
__global__ void k_wt(const float* __restrict__ w1r, const float* __restrict__ w1i,
                     const float* __restrict__ w2r, const float* __restrict__ w2i) {
    int n = C * OL * 256;
    int t = blockIdx.x * blockDim.x + threadIdx.x;
    if (t >= 2 * n) return;
    int half = (t >= n);
    int s = half ? t - n : t;
    const float* wr = half ? w2r : w1r;
    const float* wi = half ? w2i : w1i;
    int i   = s / (OL * 256);
    int rem = s - i * (OL * 256);
    int o   = rem >> 8;
    int xy  = rem & 255;
    int x = xy >> 4, y = xy & 15;
    int mode = ((half ? (16 + x) : x) << 4) + y;
    g_WT[((size_t)mode * C + i) * OL + o] = make_float2(wr[s], wi[s]);
}

// ---------------------------------------------------------------------------
// K1: forward partial DFT along w with even/odd (Hermitian) fold + f32x2 FMA.
//   Re[k] = sum_{w=0..127} E[w] cos + (-1)^k x[128];  Im[k] = sum O[w]*(-sin)
// 128 rows x 32 cols per block, 256 threads, 4x4 tiles (as 4x2 float2 pairs).
// ---------------------------------------------------------------------------
__global__ __launch_bounds__(256) void k_dftw(const float* __restrict__ x) {
    __shared__ __align__(16) float Bsc[32 * 32];   // 4KB current B panel
    __shared__ float AE[128][33];                  // 16.9KB
    __shared__ float AO[128][33];                  // 16.9KB
    int t = threadIdx.x;
    size_t row0 = (size_t)blockIdx.x * 128;

    int tr = t >> 3, tc = t & 7;          // tr 0..31, tc 0..7
    int r0 = tr * 4, c0 = tc * 4;
    bool isRe = (c0 < 16);
    float2 acc2[4][2] = {};               // [row][colpair]
    float x128[4] = {};

    for (int wc = 0; wc < 128; wc += 32) {
        {   // stage B panel (rows wc..wc+31 of g_B1, contiguous)
            const float4* src = (const float4*)(g_B1 + wc * 32);
            float4* dst = (float4*)Bsc;
            dst[t] = src[t];
        }
        // build E/O chunk: 128 rows x 32 w
        for (int i = t; i < 4096; i += 256) {
            int r = i >> 5, wl = i & 31, w = wc + wl;
            const float* xr = x + (row0 + r) * 256;
            float a = xr[w];
            float b = (w == 0) ? xr[128] : xr[256 - w];
            if (w == 0) { AE[r][wl] = a;     AO[r][wl] = b; }   // stash x[128] in AO[r][0]
            else        { AE[r][wl] = a + b; AO[r][wl] = a - b; }
        }
        __syncthreads();
        const float (*As)[33] = isRe ? AE : AO;
        #pragma unroll
        for (int kk = 0; kk < 32; kk++) {
            float4 b = *(const float4*)&Bsc[kk * 32 + c0];
            float2 b01 = make_float2(b.x, b.y);
            float2 b23 = make_float2(b.z, b.w);
            #pragma unroll
            for (int rr = 0; rr < 4; rr++) {
                float a = As[r0 + rr][kk];
                float2 aa = make_float2(a, a);
                acc2[rr][0] = ffma2(aa, b01, acc2[rr][0]);
                acc2[rr][1] = ffma2(aa, b23, acc2[rr][1]);
            }
        }
        if (wc == 0 && isRe) {   // capture x[128] stash before chunk 1 overwrites
            #pragma unroll
            for (int rr = 0; rr < 4; rr++) x128[rr] = AO[r0 + rr][0];
        }
        __syncthreads();
    }
    if (isRe) {   // (-1)^k x[128] correction, k = c0+cc
        #pragma unroll
        for (int rr = 0; rr < 4; rr++) {
            float s0 = ((c0 + 0) & 1) ? -x128[rr] : x128[rr];
            float s1 = ((c0 + 1) & 1) ? -x128[rr] : x128[rr];
            float s2 = ((c0 + 2) & 1) ? -x128[rr] : x128[rr];
            float s3 = ((c0 + 3) & 1) ? -x128[rr] : x128[rr];
            acc2[rr][0].x += s0; acc2[rr][0].y += s1;
            acc2[rr][1].x += s2; acc2[rr][1].y += s3;
        }
    }
    #pragma unroll
    for (int rr = 0; rr < 4; rr++) {
        float4 v = make_float4(acc2[rr][0].x, acc2[rr][0].y, acc2[rr][1].x, acc2[rr][1].y);
        *(float4*)&g_X1[(row0 + r0 + rr) * 32 + c0] = v;
    }
}

// ---------------------------------------------------------------------------
// K2: forward partial DFT along h with conjugate-pair fold (R7 recurrence
// version — measured best at 24.5us).
// Pair (m, 256-m), m=1..15 shares twiddles; slot 0 does m=0 and m=16.
// 512 threads = 16 k x 16 slots x 2 h-halves; partials combined via smem.
// ---------------------------------------------------------------------------
__global__ __launch_bounds__(512) void k_dfth() {
    __shared__ __align__(16) float Xs[256 * 32];   // planar rows, 32KB
    __shared__ float4 part[256];
    __shared__ float4 part16[16];
    int bc = blockIdx.x;
    int t = threadIdx.x;
    {
        const float4* src = (const float4*)(g_X1 + (size_t)bc * 8192);
        float4* dst = (float4*)Xs;
        for (int i = t; i < 2048; i += 512) dst[i] = src[i];
    }
    __syncthreads();
    int k = t & 15, slot = (t >> 4) & 15, half = t >> 8;
    int h0 = half * 128;

    float A = 0.0f, B = 0.0f, Cc = 0.0f, D = 0.0f;
    float A2 = 0.0f, B2 = 0.0f, C2 = 0.0f, D2 = 0.0f;

    if (slot != 0) {
        float sr, cr; sincospif((float)slot / 128.0f, &sr, &cr);
        float s, c;   sincospif((float)(slot * h0) / 128.0f, &s, &c);
        #pragma unroll 4
        for (int h = h0; h < h0 + 128; h++) {
            float xr = Xs[h * 32 + k];
            float xi = Xs[h * 32 + 16 + k];
            A += xr * c; B += xi * s; Cc += xi * c; D += xr * s;
            float nc = c * cr - s * sr;
            s = c * sr + s * cr;
            c = nc;
        }
    } else {
        float sr, cr; sincospif(16.0f / 128.0f, &sr, &cr);
        float s, c;   sincospif((float)(16 * h0) / 128.0f, &s, &c);
        #pragma unroll 4
        for (int h = h0; h < h0 + 128; h++) {
            float xr = Xs[h * 32 + k];
            float xi = Xs[h * 32 + 16 + k];
            A  += xr;      Cc += xi;                                 // m = 0
            A2 += xr * c; B2 += xi * s; C2 += xi * c; D2 += xr * s;  // m = 16
            float nc = c * cr - s * sr;
            s = c * sr + s * cr;
            c = nc;
        }
    }
    if (half == 1) {
        part[t - 256] = make_float4(A, B, Cc, D);
        if (slot == 0) part16[k] = make_float4(A2, B2, C2, D2);
    }
    __syncthreads();
    if (half == 0) {
        float4 p = part[t];
        A += p.x; B += p.y; Cc += p.z; D += p.w;
        float2* XF = g_XF + (size_t)bc * 512;
        if (slot == 0) {
            XF[k] = make_float2(A, Cc);                       // j=0 (ky=0)
            float4 q = part16[k];
            A2 += q.x; B2 += q.y; C2 += q.z; D2 += q.w;
            XF[16 * 16 + k] = make_float2(A2 - B2, C2 + D2);  // j=16 (ky=240)
        } else {
            XF[slot * 16 + k]        = make_float2(A + B, Cc - D);  // ky=slot
            XF[(32 - slot) * 16 + k] = make_float2(A - B, Cc + D);  // ky=256-slot
        }
    }
}

// ---------------------------------------------------------------------------
// K3: per-mode complex channel mixing [8x64]@[64x60] + pair products (ch 60..63)
// ---------------------------------------------------------------------------
__global__ __launch_bounds__(512) void k_mix() {
    __shared__ float2 Xs[512];          // [b*64+i]
    __shared__ float2 Ws[C * OL];       // [i*60+o]
    __shared__ float2 Os[8 * OL];
    int m = blockIdx.x;                 // mode = j*16+k
    int j = m >> 4, k = m & 15;
    int t = threadIdx.x;

    Xs[t] = g_XF[(size_t)t * 512 + m];  // [b*64+i][j][k] gather
    const float2* wsrc = g_WT + (size_t)m * C * OL;
    for (int i = t; i < C * OL; i += 512) Ws[i] = wsrc[i];
    __syncthreads();

    if (t < 480) {
        int b = t / 60, o = t - b * 60;
        const float2* xp = &Xs[b * 64];
        float ar = 0.0f, ai = 0.0f;
        #pragma unroll 8
        for (int i = 0; i < 64; i++) {
            float2 xv = xp[i];
            float2 wv = Ws[i * OL + o];
            ar += xv.x * wv.x - xv.y * wv.y;
            ai += xv.x * wv.y + xv.y * wv.x;
        }
        Os[t] = make_float2(ar, ai);
        g_OF[((size_t)(b * O + o) * 32 + j) * 16 + k] = make_float2(ar, ai);
    }
    __syncthreads();
    if (t < 32) {
        int b = t >> 2, p = t & 3;
        float2 u = Os[b * 60 + 2 * p];
        float2 v = Os[b * 60 + 2 * p + 1];
        float2 pr = make_float2(u.x * v.x - u.y * v.y, u.x * v.y + u.y * v.x);
        g_OF[((size_t)(b * O + 60 + p) * 32 + j) * 16 + k] = pr;
    }
}

// ---------------------------------------------------------------------------
// K45: fused inverse DFT, h-chunked for occupancy: block = (b*o, h-chunk of 64).
// 2048 blocks x 256 threads, smem ~13KB -> ~8 blocks/SM.
// Stage A: Y[h][k] = sum over 17 P/Q pair columns, rotation recurrence, f32x2.
//          PQa[m][k]=(p.re,p.im)/256, PQb[m][k]=(-q.im, q.re)/256 so that
//          acc += (c,c)*PQa + (s,s)*PQb reproduces the complex rotation.
// Stage B: real inverse along w (even/odd symmetry), (E,Od) as one f32x2 acc.
// ---------------------------------------------------------------------------
__global__ __launch_bounds__(256) void k_ifft(float* __restrict__ out) {
    __shared__ float2 PQa[17 * 16];
    __shared__ float2 PQb[17 * 16];
    __shared__ float2 Ys[64 * 17];      // h-local rows, pitch 17 (b64 access only)
    int bid = blockIdx.x;
    int bo = bid >> 2;
    int h0 = (bid & 3) * 64;
    int t = threadIdx.x;
    const float2* OFp = g_OF + (size_t)bo * 512;

    const float INV = 1.0f / 256.0f;   // stage-A normalization
    for (int idx = t; idx < 272; idx += 256) {
        int m = idx >> 4, k = idx & 15;
        float2 p, q;
        if (m == 0)       { p = OFp[k];            q = make_float2(0.0f, 0.0f); }
        else if (m == 16) { float2 o = OFp[256 + k]; p = o; q = make_float2(-o.x, -o.y); }
        else {
            float2 a = OFp[m * 16 + k], b = OFp[(32 - m) * 16 + k];
            p = make_float2(a.x + b.x, a.y + b.y);
            q = make_float2(a.x - b.x, a.y - b.y);
        }
        PQa[idx] = make_float2(p.x * INV,  p.y * INV);
        PQb[idx] = make_float2(-q.y * INV, q.x * INV);
    }
    __syncthreads();

    {   // stage A: thread = (h-local, k-quad)
        int hl = t >> 2, kq = (t & 3) * 4;
        int h = h0 + hl;
        float2 acc[4] = {};
        float sr, cr; sincospif((float)h / 128.0f, &sr, &cr);  // step e^{+i2pi h/256}
        float c = 1.0f, s = 0.0f;
        for (int m = 0; m < 17; m++) {
            float2 cc = make_float2(c, c);
            float2 ss = make_float2(s, s);
            #pragma unroll
            for (int k = 0; k < 4; k++) {
                acc[k] = ffma2(cc, PQa[m * 16 + kq + k], acc[k]);
                acc[k] = ffma2(ss, PQb[m * 16 + kq + k], acc[k]);
            }
            float nc = c * cr - s * sr;
            s = c * sr + s * cr;
            c = nc;
        }
        #pragma unroll
        for (int k = 0; k < 4; k++) Ys[hl * 17 + kq + k] = acc[k];
    }
    __syncthreads();

    // stage B: 256 threads = 128 w x 2 row-phases over the 64 local rows.
    int w = t & 127, rh = t >> 7;
    float2 ab[16];   // (Ar[k], Br[k]) packed for f32x2
    #pragma unroll
    for (int k = 0; k < 16; k++)
        ab[k] = make_float2(g_T5A[k * 128 + w], g_T5B[k * 128 + w]);

    float* ob = out + (size_t)bo * 65536;
    for (int r = rh; r < 64; r += 2) {
        float2 eo = make_float2(0.0f, 0.0f);   // (E, Od)
        #pragma unroll
        for (int k = 0; k < 16; k++)
            eo = ffma2(Ys[r * 17 + k], ab[k], eo);
        float* op = ob + (h0 + r) * 256;
        op[w] = eo.x + eo.y;
        if (w > 0) {
            op[256 - w] = eo.x - eo.y;
        } else {
            float E128 = 0.0f;   // Nyquist output column
            #pragma unroll
            for (int k = 0; k < 16; k++) {
                float a = (k == 0) ? (1.0f / 256.0f)
                                   : ((k & 1) ? (-2.0f / 256.0f) : (2.0f / 256.0f));
                E128 += Ys[r * 17 + k].x * a;
            }
            op[128] = E128;
        }
    }
}

// ---------------------------------------------------------------------------
extern "C" void kernel_launch(void* const* d_in, const int* in_sizes, int n_in,
                              void* d_out, int out_size) {
    const float* x   = (const float*)d_in[0];
    const float* w1r = (const float*)d_in[1];
    const float* w1i = (const float*)d_in[2];
    const float* w2r = (const float*)d_in[3];
    const float* w2i = (const float*)d_in[4];
    float* out = (float*)d_out;

    k_tables<<<(128 * 32 + 16 * 128 + 255) / 256, 256>>>();
    k_wt<<<(2 * C * OL * 256 + 255) / 256, 256>>>(w1r, w1i, w2r, w2i);
    k_dftw<<<R / 128, 256>>>(x);
    k_dfth<<<Bn * C, 512>>>();
    k_mix<<<NMODE, 512>>>();
    k_ifft<<<Bn * O * 4, 256>>>(out);
}

// round 12
// speedup vs baseline: 1.2715x; 1.2715x over previous
#include <cuda_runtime.h>

// Problem constants
constexpr int Bn = 8;      // batch
constexpr int C  = 64;     // cin
constexpr int O  = 64;     // cout
constexpr int OL = 60;     // cout_lin
constexpr int H  = 256;
constexpr int W  = 256;
constexpr int R  = Bn * C * H;   // 131072 rows for forward dft-w
constexpr int R2 = Bn * O * H;   // 131072 rows for inverse dft-w
constexpr int NMODE = 32 * 16;   // 512 active modes (32 ky x 16 kx)

// Scratch (static device globals; allocation-free)
__device__ __align__(16) float  g_X1[R * 32];              // [row][16 kx][re,im] interleaved
__device__ __align__(16) float2 g_XF[Bn * C * 32 * 16];    // [b][c][j][kx]
__device__ __align__(16) float2 g_WT[NMODE * C * OL];      // [mode][i][o]
__device__ __align__(16) float2 g_OF[Bn * O * 32 * 16];    // [b][o][j][kx]
__device__ __align__(16) float2 g_Y1[Bn * O * H * 16];     // [b][o][h][kx]
__device__ __align__(16) float  g_B1[256 * 32];            // fwd dft-w twiddles [w][2k|2k+1]
__device__ __align__(16) float  g_T5A[16 * 128];           // inv dft-w cos coeffs
__device__ __align__(16) float  g_T5B[16 * 128];           // inv dft-w sin coeffs

// ---------------------------------------------------------------------------
// K0a: twiddle tables
// ---------------------------------------------------------------------------
__global__ void k_tables() {
    int t = blockIdx.x * blockDim.x + threadIdx.x;
    if (t < 256 * 32) {
        int w = t >> 5, j = t & 31, k = j >> 1;
        float s, c;
        sincospif((float)(k * w) / 128.0f, &s, &c);
        g_B1[t] = (j & 1) ? -s : c;          // e^{-i2pi k w/256}: re at 2k, im at 2k+1
    } else if (t < 256 * 32 + 16 * 128) {
        int u = t - 256 * 32;
        int k = u >> 7, w = u & 127;
        float s, c;
        sincospif((float)(k * w) / 128.0f, &s, &c);
        if (k == 0) { g_T5A[u] = 1.0f / 256.0f; g_T5B[u] = 0.0f; }
        else        { g_T5A[u] = 2.0f * c / 256.0f; g_T5B[u] = -2.0f * s / 256.0f; }
    }
}

// ---------------------------------------------------------------------------
// K0b: transpose weights into per-mode [i][o] complex layout (coalesced reads)
// ---------------------------------------------------------------------------
__global__ void k_wt(const float* __restrict__ w1r, const float* __restrict__ w1i,
                     const float* __restrict__ w2r, const float* __restrict__ w2i) {
    int n = C * OL * 256;  // 983040 per tensor
    int t = blockIdx.x * blockDim.x + threadIdx.x;
    if (t >= 2 * n) return;
    int half = (t >= n);
    int s = half ? t - n : t;
    const float* wr = half ? w2r : w1r;
    const float* wi = half ? w2i : w1i;
    int i   = s / (OL * 256);
    int rem = s - i * (OL * 256);
    int o   = rem >> 8;
    int xy  = rem & 255;
    int x = xy >> 4, y = xy & 15;
    int mode = ((half ? (16 + x) : x) << 4) + y;
    g_WT[((size_t)mode * C + i) * OL + o] = make_float2(wr[s], wi[s]);
}

// ---------------------------------------------------------------------------
// K1: forward partial DFT along w.  X1[row][k] = sum_w x[row][w] e^{-i2pi kw/256}
// Register-tiled real GEMM: [64 rows x 32 cols] per block, 4x4 per thread.
// (Exact R3 version — measured within the 201us total.)
// ---------------------------------------------------------------------------
__global__ __launch_bounds__(128) void k_dftw(const float* __restrict__ x) {
    __shared__ __align__(16) float Bs[256 * 32];   // full twiddle matrix
    __shared__ float As[64][33];                    // A chunk, padded
    int t = threadIdx.x;
    size_t row0 = (size_t)blockIdx.x * 64;

    {   // stage twiddle table once
        const float4* src = (const float4*)g_B1;
        float4* dst = (float4*)Bs;
        for (int i = t; i < 2048; i += 128) dst[i] = src[i];
    }
    int tr = t >> 3, tc = t & 7;
    int r0 = tr * 4, c0 = tc * 4;
    float acc[4][4] = {};

    for (int wc = 0; wc < 256; wc += 32) {
        __syncthreads();
        #pragma unroll
        for (int it = 0; it < 4; it++) {
            int row = (t >> 3) + it * 16;
            int kk4 = (t & 7) * 4;
            float4 v = *(const float4*)&x[(row0 + row) * 256 + wc + kk4];
            As[row][kk4 + 0] = v.x; As[row][kk4 + 1] = v.y;
            As[row][kk4 + 2] = v.z; As[row][kk4 + 3] = v.w;
        }
        __syncthreads();
        #pragma unroll
        for (int kk = 0; kk < 32; kk++) {
            float4 b = *(const float4*)&Bs[(wc + kk) * 32 + c0];
            float a0 = As[r0 + 0][kk], a1 = As[r0 + 1][kk];
            float a2 = As[r0 + 2][kk], a3 = As[r0 + 3][kk];
            acc[0][0] += a0 * b.x; acc[0][1] += a0 * b.y; acc[0][2] += a0 * b.z; acc[0][3] += a0 * b.w;
            acc[1][0] += a1 * b.x; acc[1][1] += a1 * b.y; acc[1][2] += a1 * b.z; acc[1][3] += a1 * b.w;
            acc[2][0] += a2 * b.x; acc[2][1] += a2 * b.y; acc[2][2] += a2 * b.z; acc[2][3] += a2 * b.w;
            acc[3][0] += a3 * b.x; acc[3][1] += a3 * b.y; acc[3][2] += a3 * b.z; acc[3][3] += a3 * b.w;
        }
    }
    #pragma unroll
    for (int rr = 0; rr < 4; rr++) {
        float4 v = make_float4(acc[rr][0], acc[rr][1], acc[rr][2], acc[rr][3]);
        *(float4*)&g_X1[(row0 + r0 + rr) * 32 + c0] = v;
    }
}

// ---------------------------------------------------------------------------
// K2: forward partial DFT along h with conjugate-pair fold (measured 24.5us).
// Reads interleaved g_X1 rows: re at [h*32+2k], im at [h*32+2k+1].
// Pair (m, 256-m), m=1..15 shares twiddles:
//   A=sum xr*c, B=sum xi*s, C=sum xi*c, D=sum xr*s  (c,s at +angle)
//   out(m) = (A+B, C-D);  out(256-m) = (A-B, C+D)
// slot 0 handles singles m=0 and m=16 (ky=240).
// 512 threads = 16 k x 16 slots x 2 h-halves; partials combined via smem.
// ---------------------------------------------------------------------------
__global__ __launch_bounds__(512) void k_dfth() {
    __shared__ __align__(16) float Xs[256 * 32];   // interleaved rows, 32KB
    __shared__ float4 part[256];
    __shared__ float4 part16[16];
    int bc = blockIdx.x;
    int t = threadIdx.x;
    {
        const float4* src = (const float4*)(g_X1 + (size_t)bc * 8192);
        float4* dst = (float4*)Xs;
        for (int i = t; i < 2048; i += 512) dst[i] = src[i];
    }
    __syncthreads();
    int k = t & 15, slot = (t >> 4) & 15, half = t >> 8;
    int h0 = half * 128;

    float A = 0.0f, B = 0.0f, Cc = 0.0f, D = 0.0f;
    float A2 = 0.0f, B2 = 0.0f, C2 = 0.0f, D2 = 0.0f;

    if (slot != 0) {
        float sr, cr; sincospif((float)slot / 128.0f, &sr, &cr);
        float s, c;   sincospif((float)(slot * h0) / 128.0f, &s, &c);
        #pragma unroll 4
        for (int h = h0; h < h0 + 128; h++) {
            float xr = Xs[h * 32 + 2 * k];
            float xi = Xs[h * 32 + 2 * k + 1];
            A += xr * c; B += xi * s; Cc += xi * c; D += xr * s;
            float nc = c * cr - s * sr;
            s = c * sr + s * cr;
            c = nc;
        }
    } else {
        float sr, cr; sincospif(16.0f / 128.0f, &sr, &cr);
        float s, c;   sincospif((float)(16 * h0) / 128.0f, &s, &c);
        #pragma unroll 4
        for (int h = h0; h < h0 + 128; h++) {
            float xr = Xs[h * 32 + 2 * k];
            float xi = Xs[h * 32 + 2 * k + 1];
            A  += xr;      Cc += xi;                                 // m = 0
            A2 += xr * c; B2 += xi * s; C2 += xi * c; D2 += xr * s;  // m = 16
            float nc = c * cr - s * sr;
            s = c * sr + s * cr;
            c = nc;
        }
    }
    if (half == 1) {
        part[t - 256] = make_float4(A, B, Cc, D);
        if (slot == 0) part16[k] = make_float4(A2, B2, C2, D2);
    }
    __syncthreads();
    if (half == 0) {
        float4 p = part[t];
        A += p.x; B += p.y; Cc += p.z; D += p.w;
        float2* XF = g_XF + (size_t)bc * 512;
        if (slot == 0) {
            XF[k] = make_float2(A, Cc);                       // j=0 (ky=0)
            float4 q = part16[k];
            A2 += q.x; B2 += q.y; C2 += q.z; D2 += q.w;
            XF[16 * 16 + k] = make_float2(A2 - B2, C2 + D2);  // j=16 (ky=240)
        } else {
            XF[slot * 16 + k]        = make_float2(A + B, Cc - D);  // ky=slot
            XF[(32 - slot) * 16 + k] = make_float2(A - B, Cc + D);  // ky=256-slot
        }
    }
}

// ---------------------------------------------------------------------------
// K3: per-mode complex channel mixing [8x64]@[64x60] + pair products (ch 60..63)
// ---------------------------------------------------------------------------
__global__ __launch_bounds__(512) void k_mix() {
    __shared__ float2 Xs[512];          // [b*64+i]
    __shared__ float2 Ws[C * OL];       // [i*60+o]
    __shared__ float2 Os[8 * OL];
    int m = blockIdx.x;                 // mode = j*16+k
    int j = m >> 4, k = m & 15;
    int t = threadIdx.x;

    Xs[t] = g_XF[(size_t)t * 512 + m];  // [b*64+i][j][k] gather
    const float2* wsrc = g_WT + (size_t)m * C * OL;
    for (int i = t; i < C * OL; i += 512) Ws[i] = wsrc[i];
    __syncthreads();

    if (t < 480) {
        int b = t / 60, o = t - b * 60;
        const float2* xp = &Xs[b * 64];
        float ar = 0.0f, ai = 0.0f;
        #pragma unroll 8
        for (int i = 0; i < 64; i++) {
            float2 xv = xp[i];
            float2 wv = Ws[i * OL + o];
            ar += xv.x * wv.x - xv.y * wv.y;
            ai += xv.x * wv.y + xv.y * wv.x;
        }
        Os[t] = make_float2(ar, ai);
        g_OF[((size_t)(b * O + o) * 32 + j) * 16 + k] = make_float2(ar, ai);
    }
    __syncthreads();
    if (t < 32) {
        int b = t >> 2, p = t & 3;
        float2 u = Os[b * 60 + 2 * p];
        float2 v = Os[b * 60 + 2 * p + 1];
        float2 pr = make_float2(u.x * v.x - u.y * v.y, u.x * v.y + u.y * v.x);
        g_OF[((size_t)(b * O + 60 + p) * 32 + j) * 16 + k] = pr;
    }
}

// ---------------------------------------------------------------------------
// K4: inverse DFT along h.  Y1[h][k] = (1/256) sum_j OF[j][k] e^{+i2pi ky(j) h/256}
// One block per (b,o); thread = h; 16 complex accumulators.  (Exact R3 version.)
// ---------------------------------------------------------------------------
__global__ __launch_bounds__(256) void k_idfth() {
    __shared__ __align__(16) float2 OFs[32][16];
    int bo = blockIdx.x;
    int h = threadIdx.x;
    {
        const float4* src = (const float4*)(g_OF + (size_t)bo * 512);
        float4* dst = (float4*)OFs;
        for (int i = h; i < 256; i += 256) dst[i] = src[i];
    }
    __syncthreads();
    float2 acc[16];
    #pragma unroll
    for (int k = 0; k < 16; k++) acc[k] = make_float2(0.0f, 0.0f);
    #pragma unroll 4
    for (int j = 0; j < 32; j++) {
        int ky = (j < 16) ? j : (224 + j);
        float s, c;
        sincospif((float)(ky * h) / 128.0f, &s, &c);   // e^{+i2pi ky h/256}
        #pragma unroll
        for (int k = 0; k < 16; k++) {
            float2 ov = OFs[j][k];
            acc[k].x += ov.x * c - ov.y * s;
            acc[k].y += ov.x * s + ov.y * c;
        }
    }
    float2* outp = g_Y1 + ((size_t)bo * 256 + h) * 16;
    #pragma unroll
    for (int k = 0; k < 16; k++)
        outp[k] = make_float2(acc[k].x * (1.0f / 256.0f), acc[k].y * (1.0f / 256.0f));
}

// ---------------------------------------------------------------------------
// K5: inverse real DFT along w (c2r semantics: imag of DC/Nyquist ignored).
// Even/odd symmetry: compute w and 256-w together -> work halved.
// Block handles 32 rows; thread = w in 0..127.  (Exact R3 version.)
// ---------------------------------------------------------------------------
__global__ __launch_bounds__(128) void k_idftw(float* __restrict__ out) {
    __shared__ __align__(16) float Ta[16 * 128];
    __shared__ __align__(16) float Tb[16 * 128];
    __shared__ __align__(16) float2 Ys[32][16];
    int t = threadIdx.x;
    size_t row0 = (size_t)blockIdx.x * 32;
    {
        const float4* sa = (const float4*)g_T5A;
        const float4* sb = (const float4*)g_T5B;
        float4* da = (float4*)Ta; float4* db = (float4*)Tb;
        for (int i = t; i < 512; i += 128) { da[i] = sa[i]; db[i] = sb[i]; }
        const float4* sy = (const float4*)(g_Y1 + row0 * 16);
        float4* dy = (float4*)Ys;
        for (int i = t; i < 256; i += 128) dy[i] = sy[i];
    }
    __syncthreads();
    float Ar[16], Br[16];
    #pragma unroll
    for (int k = 0; k < 16; k++) { Ar[k] = Ta[k * 128 + t]; Br[k] = Tb[k * 128 + t]; }

    for (int r = 0; r < 32; r++) {
        float E = 0.0f, Od = 0.0f;
        #pragma unroll
        for (int k = 0; k < 16; k++) {
            float2 y = Ys[r][k];
            E  += y.x * Ar[k];   // even (cos) part
            Od += y.y * Br[k];   // odd (sin) part
        }
        float* op = out + (row0 + r) * 256;
        op[t] = E + Od;
        if (t > 0) {
            op[256 - t] = E - Od;
        } else {
            float E128 = 0.0f;   // w = 128 (Nyquist column of the output grid)
            #pragma unroll
            for (int k = 0; k < 16; k++) {
                float a = (k == 0) ? (1.0f / 256.0f)
                                   : ((k & 1) ? (-2.0f / 256.0f) : (2.0f / 256.0f));
                E128 += Ys[r][k].x * a;
            }
            op[128] = E128;
        }
    }
}

// ---------------------------------------------------------------------------
extern "C" void kernel_launch(void* const* d_in, const int* in_sizes, int n_in,
                              void* d_out, int out_size) {
    const float* x   = (const float*)d_in[0];
    const float* w1r = (const float*)d_in[1];
    const float* w1i = (const float*)d_in[2];
    const float* w2r = (const float*)d_in[3];
    const float* w2i = (const float*)d_in[4];
    float* out = (float*)d_out;

    k_tables<<<(256 * 32 + 16 * 128 + 255) / 256, 256>>>();
    k_wt<<<(2 * C * OL * 256 + 255) / 256, 256>>>(w1r, w1i, w2r, w2i);
    k_dftw<<<R / 64, 128>>>(x);
    k_dfth<<<Bn * C, 512>>>();
    k_mix<<<NMODE, 512>>>();
    k_idfth<<<Bn * O, 256>>>();
    k_idftw<<<R2 / 32, 128>>>(out);
}

// round 13
// speedup vs baseline: 1.3265x; 1.0432x over previous
#include <cuda_runtime.h>

// Problem constants
constexpr int Bn = 8;      // batch
constexpr int C  = 64;     // cin
constexpr int O  = 64;     // cout
constexpr int OL = 60;     // cout_lin
constexpr int H  = 256;
constexpr int W  = 256;
constexpr int R  = Bn * C * H;   // 131072 rows for forward dft-w
constexpr int R2 = Bn * O * H;   // 131072 rows for inverse dft-w
constexpr int NMODE = 32 * 16;   // 512 active modes (32 ky x 16 kx)

// Scratch (static device globals; allocation-free)
__device__ __align__(16) float  g_X1[R * 32];              // [row][16 kx][re,im] interleaved
__device__ __align__(16) float2 g_XF[Bn * C * 32 * 16];    // [b][c][j][kx]
__device__ __align__(16) float2 g_WT[NMODE * C * OL];      // [mode][i][o]
__device__ __align__(16) float2 g_OF[Bn * O * 32 * 16];    // [b][o][j][kx]
__device__ __align__(16) float2 g_Y1[Bn * O * H * 16];     // [b][o][h][kx]
__device__ __align__(16) float  g_B1[256 * 32];            // fwd dft-w twiddles [w][2k|2k+1]
__device__ __align__(16) float  g_T5A[16 * 128];           // inv dft-w cos coeffs
__device__ __align__(16) float  g_T5B[16 * 128];           // inv dft-w sin coeffs

// ---------------------------------------------------------------------------
// K0a: twiddle tables
// ---------------------------------------------------------------------------
__global__ void k_tables() {
    int t = blockIdx.x * blockDim.x + threadIdx.x;
    if (t < 256 * 32) {
        int w = t >> 5, j = t & 31, k = j >> 1;
        float s, c;
        sincospif((float)(k * w) / 128.0f, &s, &c);
        g_B1[t] = (j & 1) ? -s : c;          // e^{-i2pi k w/256}: re at 2k, im at 2k+1
    } else if (t < 256 * 32 + 16 * 128) {
        int u = t - 256 * 32;
        int k = u >> 7, w = u & 127;
        float s, c;
        sincospif((float)(k * w) / 128.0f, &s, &c);
        if (k == 0) { g_T5A[u] = 1.0f / 256.0f; g_T5B[u] = 0.0f; }
        else        { g_T5A[u] = 2.0f * c / 256.0f; g_T5B[u] = -2.0f * s / 256.0f; }
    }
}

// ---------------------------------------------------------------------------
// K0b: transpose weights into per-mode [i][o] complex layout (coalesced reads)
// ---------------------------------------------------------------------------
__global__ void k_wt(const float* __restrict__ w1r, const float* __restrict__ w1i,
                     const float* __restrict__ w2r, const float* __restrict__ w2i) {
    int n = C * OL * 256;  // 983040 per tensor
    int t = blockIdx.x * blockDim.x + threadIdx.x;
    if (t >= 2 * n) return;
    int half = (t >= n);
    int s = half ? t - n : t;
    const float* wr = half ? w2r : w1r;
    const float* wi = half ? w2i : w1i;
    int i   = s / (OL * 256);
    int rem = s - i * (OL * 256);
    int o   = rem >> 8;
    int xy  = rem & 255;
    int x = xy >> 4, y = xy & 15;
    int mode = ((half ? (16 + x) : x) << 4) + y;
    g_WT[((size_t)mode * C + i) * OL + o] = make_float2(wr[s], wi[s]);
}

// ---------------------------------------------------------------------------
// K1: forward partial DFT along w.  X1[row][k] = sum_w x[row][w] e^{-i2pi kw/256}
// Register-tiled real GEMM: [64 rows x 32 cols] per block, 4x4 per thread.
// (Exact R3 version — measured within the 194.6us total.)
// ---------------------------------------------------------------------------
__global__ __launch_bounds__(128) void k_dftw(const float* __restrict__ x) {
    __shared__ __align__(16) float Bs[256 * 32];   // full twiddle matrix
    __shared__ float As[64][33];                    // A chunk, padded
    int t = threadIdx.x;
    size_t row0 = (size_t)blockIdx.x * 64;

    {   // stage twiddle table once
        const float4* src = (const float4*)g_B1;
        float4* dst = (float4*)Bs;
        for (int i = t; i < 2048; i += 128) dst[i] = src[i];
    }
    int tr = t >> 3, tc = t & 7;
    int r0 = tr * 4, c0 = tc * 4;
    float acc[4][4] = {};

    for (int wc = 0; wc < 256; wc += 32) {
        __syncthreads();
        #pragma unroll
        for (int it = 0; it < 4; it++) {
            int row = (t >> 3) + it * 16;
            int kk4 = (t & 7) * 4;
            float4 v = *(const float4*)&x[(row0 + row) * 256 + wc + kk4];
            As[row][kk4 + 0] = v.x; As[row][kk4 + 1] = v.y;
            As[row][kk4 + 2] = v.z; As[row][kk4 + 3] = v.w;
        }
        __syncthreads();
        #pragma unroll
        for (int kk = 0; kk < 32; kk++) {
            float4 b = *(const float4*)&Bs[(wc + kk) * 32 + c0];
            float a0 = As[r0 + 0][kk], a1 = As[r0 + 1][kk];
            float a2 = As[r0 + 2][kk], a3 = As[r0 + 3][kk];
            acc[0][0] += a0 * b.x; acc[0][1] += a0 * b.y; acc[0][2] += a0 * b.z; acc[0][3] += a0 * b.w;
            acc[1][0] += a1 * b.x; acc[1][1] += a1 * b.y; acc[1][2] += a1 * b.z; acc[1][3] += a1 * b.w;
            acc[2][0] += a2 * b.x; acc[2][1] += a2 * b.y; acc[2][2] += a2 * b.z; acc[2][3] += a2 * b.w;
            acc[3][0] += a3 * b.x; acc[3][1] += a3 * b.y; acc[3][2] += a3 * b.z; acc[3][3] += a3 * b.w;
        }
    }
    #pragma unroll
    for (int rr = 0; rr < 4; rr++) {
        float4 v = make_float4(acc[rr][0], acc[rr][1], acc[rr][2], acc[rr][3]);
        *(float4*)&g_X1[(row0 + r0 + rr) * 32 + c0] = v;
    }
}

// ---------------------------------------------------------------------------
// K2: forward partial DFT along h with conjugate-pair fold (measured 24.0us).
// Reads interleaved g_X1 rows: re at [h*32+2k], im at [h*32+2k+1].
// Pair (m, 256-m), m=1..15 shares twiddles:
//   A=sum xr*c, B=sum xi*s, C=sum xi*c, D=sum xr*s  (c,s at +angle)
//   out(m) = (A+B, C-D);  out(256-m) = (A-B, C+D)
// slot 0 handles singles m=0 and m=16 (ky=240).
// 512 threads = 16 k x 16 slots x 2 h-halves; partials combined via smem.
// ---------------------------------------------------------------------------
__global__ __launch_bounds__(512) void k_dfth() {
    __shared__ __align__(16) float Xs[256 * 32];   // interleaved rows, 32KB
    __shared__ float4 part[256];
    __shared__ float4 part16[16];
    int bc = blockIdx.x;
    int t = threadIdx.x;
    {
        const float4* src = (const float4*)(g_X1 + (size_t)bc * 8192);
        float4* dst = (float4*)Xs;
        for (int i = t; i < 2048; i += 512) dst[i] = src[i];
    }
    __syncthreads();
    int k = t & 15, slot = (t >> 4) & 15, half = t >> 8;
    int h0 = half * 128;

    float A = 0.0f, B = 0.0f, Cc = 0.0f, D = 0.0f;
    float A2 = 0.0f, B2 = 0.0f, C2 = 0.0f, D2 = 0.0f;

    if (slot != 0) {
        float sr, cr; sincospif((float)slot / 128.0f, &sr, &cr);
        float s, c;   sincospif((float)(slot * h0) / 128.0f, &s, &c);
        #pragma unroll 4
        for (int h = h0; h < h0 + 128; h++) {
            float xr = Xs[h * 32 + 2 * k];
            float xi = Xs[h * 32 + 2 * k + 1];
            A += xr * c; B += xi * s; Cc += xi * c; D += xr * s;
            float nc = c * cr - s * sr;
            s = c * sr + s * cr;
            c = nc;
        }
    } else {
        float sr, cr; sincospif(16.0f / 128.0f, &sr, &cr);
        float s, c;   sincospif((float)(16 * h0) / 128.0f, &s, &c);
        #pragma unroll 4
        for (int h = h0; h < h0 + 128; h++) {
            float xr = Xs[h * 32 + 2 * k];
            float xi = Xs[h * 32 + 2 * k + 1];
            A  += xr;      Cc += xi;                                 // m = 0
            A2 += xr * c; B2 += xi * s; C2 += xi * c; D2 += xr * s;  // m = 16
            float nc = c * cr - s * sr;
            s = c * sr + s * cr;
            c = nc;
        }
    }
    if (half == 1) {
        part[t - 256] = make_float4(A, B, Cc, D);
        if (slot == 0) part16[k] = make_float4(A2, B2, C2, D2);
    }
    __syncthreads();
    if (half == 0) {
        float4 p = part[t];
        A += p.x; B += p.y; Cc += p.z; D += p.w;
        float2* XF = g_XF + (size_t)bc * 512;
        if (slot == 0) {
            XF[k] = make_float2(A, Cc);                       // j=0 (ky=0)
            float4 q = part16[k];
            A2 += q.x; B2 += q.y; C2 += q.z; D2 += q.w;
            XF[16 * 16 + k] = make_float2(A2 - B2, C2 + D2);  // j=16 (ky=240)
        } else {
            XF[slot * 16 + k]        = make_float2(A + B, Cc - D);  // ky=slot
            XF[(32 - slot) * 16 + k] = make_float2(A - B, Cc + D);  // ky=256-slot
        }
    }
}

// ---------------------------------------------------------------------------
// K3: per-mode complex channel mixing [8x64]@[64x60] + pair products (ch 60..63)
// ---------------------------------------------------------------------------
__global__ __launch_bounds__(512) void k_mix() {
    __shared__ float2 Xs[512];          // [b*64+i]
    __shared__ float2 Ws[C * OL];       // [i*60+o]
    __shared__ float2 Os[8 * OL];
    int m = blockIdx.x;                 // mode = j*16+k
    int j = m >> 4, k = m & 15;
    int t = threadIdx.x;

    Xs[t] = g_XF[(size_t)t * 512 + m];  // [b*64+i][j][k] gather
    const float2* wsrc = g_WT + (size_t)m * C * OL;
    for (int i = t; i < C * OL; i += 512) Ws[i] = wsrc[i];
    __syncthreads();

    if (t < 480) {
        int b = t / 60, o = t - b * 60;
        const float2* xp = &Xs[b * 64];
        float ar = 0.0f, ai = 0.0f;
        #pragma unroll 8
        for (int i = 0; i < 64; i++) {
            float2 xv = xp[i];
            float2 wv = Ws[i * OL + o];
            ar += xv.x * wv.x - xv.y * wv.y;
            ai += xv.x * wv.y + xv.y * wv.x;
        }
        Os[t] = make_float2(ar, ai);
        g_OF[((size_t)(b * O + o) * 32 + j) * 16 + k] = make_float2(ar, ai);
    }
    __syncthreads();
    if (t < 32) {
        int b = t >> 2, p = t & 3;
        float2 u = Os[b * 60 + 2 * p];
        float2 v = Os[b * 60 + 2 * p + 1];
        float2 pr = make_float2(u.x * v.x - u.y * v.y, u.x * v.y + u.y * v.x);
        g_OF[((size_t)(b * O + 60 + p) * 32 + j) * 16 + k] = pr;
    }
}

// ---------------------------------------------------------------------------
// K4: inverse DFT along h with conjugate-pair fold (P/Q columns, verified in R9).
// Y1[h][k] = (1/256) sum over 17 pair-columns: c*P + i*s*Q, where
//   m=0:      P = OF[0],           Q = 0
//   m=1..15:  P = OF[m]+OF[32-m],  Q = OF[m]-OF[32-m]
//   m=16:     P = OF[16] (ky=240), Q = -OF[16]    (e^{-i16h} = conj rotation)
//   Re += c*P.re - s*Q.im ;  Im += c*P.im + s*Q.re
// Rotation recurrence e^{+i2pi h/256} per m step; ONE sincospif per thread.
// One block per (b,o); thread = h; 16 complex accumulators.
// ---------------------------------------------------------------------------
__global__ __launch_bounds__(256) void k_idfth() {
    __shared__ __align__(16) float4 PQ[17 * 16];    // (P.re, P.im, Q.re, Q.im) * (1/256)
    int bo = blockIdx.x;
    int h = threadIdx.x;
    const float2* OFp = g_OF + (size_t)bo * 512;

    const float INV = 1.0f / 256.0f;
    for (int idx = h; idx < 272; idx += 256) {
        int m = idx >> 4, k = idx & 15;
        float2 p, q;
        if (m == 0)       { p = OFp[k];              q = make_float2(0.0f, 0.0f); }
        else if (m == 16) { float2 o = OFp[256 + k]; p = o; q = make_float2(-o.x, -o.y); }
        else {
            float2 a = OFp[m * 16 + k], b = OFp[(32 - m) * 16 + k];
            p = make_float2(a.x + b.x, a.y + b.y);
            q = make_float2(a.x - b.x, a.y - b.y);
        }
        PQ[idx] = make_float4(p.x * INV, p.y * INV, q.x * INV, q.y * INV);
    }
    __syncthreads();

    float2 acc[16];
    #pragma unroll
    for (int k = 0; k < 16; k++) acc[k] = make_float2(0.0f, 0.0f);
    float sr, cr; sincospif((float)h / 128.0f, &sr, &cr);  // step e^{+i2pi h/256}
    float c = 1.0f, s = 0.0f;
    for (int m = 0; m < 17; m++) {
        #pragma unroll
        for (int k = 0; k < 16; k++) {
            float4 pq = PQ[m * 16 + k];    // warp-uniform -> broadcast LDS.128
            acc[k].x += c * pq.x - s * pq.w;
            acc[k].y += c * pq.y + s * pq.z;
        }
        float nc = c * cr - s * sr;
        s = c * sr + s * cr;
        c = nc;
    }
    float2* outp = g_Y1 + ((size_t)bo * 256 + h) * 16;
    #pragma unroll
    for (int k = 0; k < 16; k++) outp[k] = acc[k];
}

// ---------------------------------------------------------------------------
// K5: inverse real DFT along w (c2r semantics: imag of DC/Nyquist ignored).
// Even/odd symmetry: compute w and 256-w together -> work halved.
// Block handles 32 rows; thread = w in 0..127.  (Exact R3 version.)
// ---------------------------------------------------------------------------
__global__ __launch_bounds__(128) void k_idftw(float* __restrict__ out) {
    __shared__ __align__(16) float Ta[16 * 128];
    __shared__ __align__(16) float Tb[16 * 128];
    __shared__ __align__(16) float2 Ys[32][16];
    int t = threadIdx.x;
    size_t row0 = (size_t)blockIdx.x * 32;
    {
        const float4* sa = (const float4*)g_T5A;
        const float4* sb = (const float4*)g_T5B;
        float4* da = (float4*)Ta; float4* db = (float4*)Tb;
        for (int i = t; i < 512; i += 128) { da[i] = sa[i]; db[i] = sb[i]; }
        const float4* sy = (const float4*)(g_Y1 + row0 * 16);
        float4* dy = (float4*)Ys;
        for (int i = t; i < 256; i += 128) dy[i] = sy[i];
    }
    __syncthreads();
    float Ar[16], Br[16];
    #pragma unroll
    for (int k = 0; k < 16; k++) { Ar[k] = Ta[k * 128 + t]; Br[k] = Tb[k * 128 + t]; }

    for (int r = 0; r < 32; r++) {
        float E = 0.0f, Od = 0.0f;
        #pragma unroll
        for (int k = 0; k < 16; k++) {
            float2 y = Ys[r][k];
            E  += y.x * Ar[k];   // even (cos) part
            Od += y.y * Br[k];   // odd (sin) part
        }
        float* op = out + (row0 + r) * 256;
        op[t] = E + Od;
        if (t > 0) {
            op[256 - t] = E - Od;
        } else {
            float E128 = 0.0f;   // w = 128 (Nyquist column of the output grid)
            #pragma unroll
            for (int k = 0; k < 16; k++) {
                float a = (k == 0) ? (1.0f / 256.0f)
                                   : ((k & 1) ? (-2.0f / 256.0f) : (2.0f / 256.0f));
                E128 += Ys[r][k].x * a;
            }
            op[128] = E128;
        }
    }
}

// ---------------------------------------------------------------------------
extern "C" void kernel_launch(void* const* d_in, const int* in_sizes, int n_in,
                              void* d_out, int out_size) {
    const float* x   = (const float*)d_in[0];
    const float* w1r = (const float*)d_in[1];
    const float* w1i = (const float*)d_in[2];
    const float* w2r = (const float*)d_in[3];
    const float* w2i = (const float*)d_in[4];
    float* out = (float*)d_out;

    k_tables<<<(256 * 32 + 16 * 128 + 255) / 256, 256>>>();
    k_wt<<<(2 * C * OL * 256 + 255) / 256, 256>>>(w1r, w1i, w2r, w2i);
    k_dftw<<<R / 64, 128>>>(x);
    k_dfth<<<Bn * C, 512>>>();
    k_mix<<<NMODE, 512>>>();
    k_idfth<<<Bn * O, 256>>>();
    k_idftw<<<R2 / 32, 128>>>(out);
}